// round 11
// baseline (speedup 1.0000x reference)
#include <cuda_runtime.h>
#include <cuda_bf16.h>
#include <math_constants.h>
#include <cstdint>

// Tropical (max-plus) matmul via log-sum-exp + bf16 mma.sync GEMM.
//   y[b,i] = mx_b + T*( ln( sum_j e^{(x_bj-mx_b)/T + CA} * e^{W_ij/T} ) - CA )
// T = 0.005, CA = 20.
//
// R9: zero-sync single kernel (R8 structure). Prep rebalanced:
//  - exp split: 8 values/row on MUFU ex2, 8 on packed f32x2 FMA poly
//  - explicit next-row LDG prefetch (software pipeline)
//  - STS.128 batched image stores

#define KDIM 512
#define NDIM 512
#define T_VAL 0.005f
#define CA_SHIFT 20.0f
#define C1_X 288.539008f   // (1/T)*log2(e)
#define C0_X 28.8539008f   // CA*log2(e)

#define RSTR 1040          // bytes/row in smem image (260 words ≡ 4 mod 32: conflict-free)
#define SM_A 0
#define SM_B (128 * RSTR)            // 133120
#define SM_MX (SM_B + 64 * RSTR)     // 199680
#define SMEM_TOTAL (SM_MX + 512)     // 200192 B

// ---------------- packed f32x2 helpers (sm_103a) ----------------

__device__ __forceinline__ uint64_t pk2(float a, float b)
{ uint64_t r; asm("mov.b64 %0,{%1,%2};" : "=l"(r) : "f"(a), "f"(b)); return r; }

__device__ __forceinline__ void upk2(uint64_t v, float& a, float& b)
{ asm("mov.b64 {%0,%1},%2;" : "=f"(a), "=f"(b) : "l"(v)); }

__device__ __forceinline__ uint64_t f2add(uint64_t a, uint64_t b)
{ uint64_t d; asm("add.rn.f32x2 %0,%1,%2;" : "=l"(d) : "l"(a), "l"(b)); return d; }

__device__ __forceinline__ uint64_t f2fma(uint64_t a, uint64_t b, uint64_t c)
{ uint64_t d; asm("fma.rn.f32x2 %0,%1,%2,%3;" : "=l"(d) : "l"(a), "l"(b), "l"(c)); return d; }

struct P2 {   // packed constants for the poly path
    uint64_t mag, negmag, neg1, c4, c3, c2, c1, one;
    __device__ __forceinline__ void init() {
        mag    = pk2( 12582912.0f,  12582912.0f);
        negmag = pk2(-12582912.0f, -12582912.0f);
        neg1   = pk2(-1.0f, -1.0f);
        c4     = pk2(0.00961813f, 0.00961813f);
        c3     = pk2(0.05550411f, 0.05550411f);
        c2     = pk2(0.24022651f, 0.24022651f);
        c1     = pk2(0.69314718f, 0.69314718f);
        one    = pk2(1.0f, 1.0f);
    }
};

__device__ __forceinline__ float ex2_approx(float t)
{ float r; asm("ex2.approx.f32 %0, %1;" : "=f"(r) : "f"(t)); return r; }

__device__ __forceinline__ uint32_t pack_bf2(float a, float b)
{ __nv_bfloat162 h = __floats2bfloat162_rn(a, b); return *reinterpret_cast<uint32_t*>(&h); }

// exp2 of a clamped pair via packed FMA poly; returns bf16x2
__device__ __forceinline__ uint32_t exp2_pair_bf16(float t0, float t1, const P2& K)
{
    t0 = fmaxf(t0, -126.0f);
    t1 = fmaxf(t1, -126.0f);
    uint64_t tp = pk2(t0, t1);
    uint64_t rp = f2add(tp, K.mag);        // r = t + M (n encoded in mantissa)
    uint64_t np = f2add(rp, K.negmag);     // n = r - M (float)
    uint64_t fp = f2fma(np, K.neg1, tp);   // f = t - n, in [-0.5, 0.5]
    uint64_t p  = f2fma(K.c4, fp, K.c3);
    p = f2fma(p, fp, K.c2);
    p = f2fma(p, fp, K.c1);
    p = f2fma(p, fp, K.one);               // ~2^f
    float r0, r1, p0, p1;
    upk2(rp, r0, r1);
    upk2(p,  p0, p1);
    int iv0 = __float_as_int(r0) - 0x4B400000;
    int iv1 = __float_as_int(r1) - 0x4B400000;
    float e0 = __int_as_float(__float_as_int(p0) + (iv0 << 23));
    float e1 = __int_as_float(__float_as_int(p1) + (iv1 << 23));
    return pack_bf2(e0, e1);
}

__device__ __forceinline__ float fast_ln(float v)
{
    int   iv = __float_as_int(v);
    float e  = (float)((iv >> 23) - 127);
    float m  = __int_as_float((iv & 0x7FFFFF) | 0x3F800000);
    float p  = -0.0565708f;
    p = fmaf(p, m,  0.4471796f);
    p = fmaf(p, m, -1.4699568f);
    p = fmaf(p, m,  2.8212026f);
    p = fmaf(p, m, -1.7417939f);
    return fmaf(e, 0.6931472f, p);
}

// ---------------- mma helpers ----------------

__device__ __forceinline__ void ldsm_x4(uint32_t& r0, uint32_t& r1,
                                        uint32_t& r2, uint32_t& r3, uint32_t a)
{
    asm volatile("ldmatrix.sync.aligned.m8n8.x4.shared.b16 {%0,%1,%2,%3}, [%4];"
                 : "=r"(r0), "=r"(r1), "=r"(r2), "=r"(r3) : "r"(a));
}

__device__ __forceinline__ void mma_bf16(float* c, const uint32_t* a, uint32_t b0, uint32_t b1)
{
    asm volatile(
        "mma.sync.aligned.m16n8k16.row.col.f32.bf16.bf16.f32 "
        "{%0,%1,%2,%3},{%4,%5,%6,%7},{%8,%9},{%0,%1,%2,%3};"
        : "+f"(c[0]), "+f"(c[1]), "+f"(c[2]), "+f"(c[3])
        : "r"(a[0]), "r"(a[1]), "r"(a[2]), "r"(a[3]), "r"(b0), "r"(b1));
}

// ---------------- fused kernel, grid (8,16) x 512 threads ----------------

__global__ __launch_bounds__(512)
void tropical_kernel(const float* __restrict__ x, const float* __restrict__ W,
                     float* __restrict__ out)
{
    extern __shared__ __align__(16) unsigned char smem[];
    float* smx = (float*)(smem + SM_MX);

    const int tid  = threadIdx.x;
    const int warp = tid >> 5, lane = tid & 31;
    const int bm   = blockIdx.y * 128, bn = blockIdx.x * 64;

    P2 K; K.init();

    // ---- phase 1: prep 192 rows (128 A + 64 B), 12/warp, 1-row pipelined ----
    // Per-lane ownership: elements [8*lane, 8*lane+8) and [256+8*lane, +8).
    // Loads: float4 ids {2L, 2L+1, 2L+64, 2L+65}. Store: 2x STS.128 per row.
    const int i0 = 2 * lane, i1 = 2 * lane + 1, i2 = 2 * lane + 64, i3 = 2 * lane + 65;

    auto row_ptr = [&](int vr) -> const float4* {
        return (vr < 128) ? (const float4*)(x + (size_t)(bm + vr) * KDIM)
                          : (const float4*)(W + (size_t)(bn + vr - 128) * KDIM);
    };

    float4 c0, c1, c2, c3;
    {
        const float4* rp = row_ptr(warp);
        c0 = rp[i0]; c1 = rp[i1]; c2 = rp[i2]; c3 = rp[i3];
    }

    #pragma unroll 1
    for (int i = 0; i < 12; i++) {
        const int vr = warp + 16 * i;
        float4 n0, n1, n2, n3;
        if (i < 11) {                    // prefetch next row (overlaps exp below)
            const float4* rp = row_ptr(warp + 16 * (i + 1));
            n0 = rp[i0]; n1 = rp[i1]; n2 = rp[i2]; n3 = rp[i3];
        }

        float base;
        unsigned char* orow;
        if (vr < 128) {
            float m = fmaxf(fmaxf(fmaxf(c0.x, c0.y), fmaxf(c0.z, c0.w)),
                            fmaxf(fmaxf(c1.x, c1.y), fmaxf(c1.z, c1.w)));
            m = fmaxf(m, fmaxf(fmaxf(c2.x, c2.y), fmaxf(c2.z, c2.w)));
            m = fmaxf(m, fmaxf(fmaxf(c3.x, c3.y), fmaxf(c3.z, c3.w)));
            #pragma unroll
            for (int o = 16; o; o >>= 1) m = fmaxf(m, __shfl_xor_sync(0xffffffffu, m, o));
            if (lane == 0) smx[vr] = m;
            base = fmaf(-m, C1_X, C0_X);
            orow = smem + SM_A + vr * RSTR;
        } else {
            base = 0.0f;
            orow = smem + SM_B + (vr - 128) * RSTR;
        }

        // first 8 values (c0,c1): packed FMA poly path
        uint4 q;
        q.x = exp2_pair_bf16(fmaf(c0.x, C1_X, base), fmaf(c0.y, C1_X, base), K);
        q.y = exp2_pair_bf16(fmaf(c0.z, C1_X, base), fmaf(c0.w, C1_X, base), K);
        q.z = exp2_pair_bf16(fmaf(c1.x, C1_X, base), fmaf(c1.y, C1_X, base), K);
        q.w = exp2_pair_bf16(fmaf(c1.z, C1_X, base), fmaf(c1.w, C1_X, base), K);
        *(uint4*)(orow + 16 * lane) = q;

        // second 8 values (c2,c3): MUFU ex2 path
        uint4 r;
        r.x = pack_bf2(ex2_approx(fmaf(c2.x, C1_X, base)), ex2_approx(fmaf(c2.y, C1_X, base)));
        r.y = pack_bf2(ex2_approx(fmaf(c2.z, C1_X, base)), ex2_approx(fmaf(c2.w, C1_X, base)));
        r.z = pack_bf2(ex2_approx(fmaf(c3.x, C1_X, base)), ex2_approx(fmaf(c3.y, C1_X, base)));
        r.w = pack_bf2(ex2_approx(fmaf(c3.z, C1_X, base)), ex2_approx(fmaf(c3.w, C1_X, base)));
        *(uint4*)(orow + 512 + 16 * lane) = r;

        c0 = n0; c1 = n1; c2 = n2; c3 = n3;
    }
    __syncthreads();   // the ONLY pre-GEMM sync

    // ---- phase 2: full-K mainloop, 32 k16 steps, no barriers ----
    const int wm = warp & 3, wn = warp >> 2;     // 4x4 warps, 32x16 warp tile
    const int lr = lane & 15;
    const int lh = (lane >> 4) * 8;

    uint32_t aaddr[2], baddr;
    #pragma unroll
    for (int mt = 0; mt < 2; mt++)
        aaddr[mt] = (uint32_t)__cvta_generic_to_shared(
            smem + SM_A + (wm * 32 + mt * 16 + lr) * RSTR + lh * 2);
    baddr = (uint32_t)__cvta_generic_to_shared(
        smem + SM_B + (wn * 16 + lr) * RSTR + lh * 2);

    float acc[2][2][4];
    #pragma unroll
    for (int i = 0; i < 2; i++)
        #pragma unroll
        for (int j = 0; j < 2; j++)
            #pragma unroll
            for (int k = 0; k < 4; k++) acc[i][j][k] = 0.f;

    uint32_t fa[2][2][4], fb[2][4];
    #pragma unroll
    for (int mt = 0; mt < 2; mt++)
        ldsm_x4(fa[0][mt][0], fa[0][mt][1], fa[0][mt][2], fa[0][mt][3], aaddr[mt]);
    ldsm_x4(fb[0][0], fb[0][1], fb[0][2], fb[0][3], baddr);

    #pragma unroll 4
    for (int kk = 0; kk < 32; kk++) {
        const int cf = kk & 1, nf = cf ^ 1;
        if (kk + 1 < 32) {
            const uint32_t off = (uint32_t)(kk + 1) * 32u;   // +16 cols = 32 B
            #pragma unroll
            for (int mt = 0; mt < 2; mt++)
                ldsm_x4(fa[nf][mt][0], fa[nf][mt][1], fa[nf][mt][2], fa[nf][mt][3],
                        aaddr[mt] + off);
            ldsm_x4(fb[nf][0], fb[nf][1], fb[nf][2], fb[nf][3], baddr + off);
        }
        #pragma unroll
        for (int mt = 0; mt < 2; mt++) {
            mma_bf16(acc[mt][0], fa[cf][mt], fb[cf][0], fb[cf][2]);
            mma_bf16(acc[mt][1], fa[cf][mt], fb[cf][1], fb[cf][3]);
        }
    }

    // ---- epilogue: ln -> smem stage (reuse A image) -> coalesced stores ----
    const int g = lane >> 2, t4 = lane & 3;
    float mx0[2], mx1[2];
    #pragma unroll
    for (int mt = 0; mt < 2; mt++) {
        mx0[mt] = smx[wm * 32 + mt * 16 + g];
        mx1[mt] = smx[wm * 32 + mt * 16 + g + 8];
    }
    __syncthreads();                       // all smem reads done before aliasing
    float* stg = (float*)smem;             // 128 rows x 68 floats

    #pragma unroll
    for (int mt = 0; mt < 2; mt++) {
        const int r0 = wm * 32 + mt * 16 + g;
        #pragma unroll
        for (int nt = 0; nt < 2; nt++) {
            const int c0i = wn * 16 + nt * 8 + 2 * t4;
            stg[r0 * 68 + c0i]           = mx0[mt] + T_VAL * (fast_ln(acc[mt][nt][0]) - CA_SHIFT);
            stg[r0 * 68 + c0i + 1]       = mx0[mt] + T_VAL * (fast_ln(acc[mt][nt][1]) - CA_SHIFT);
            stg[(r0 + 8) * 68 + c0i]     = mx1[mt] + T_VAL * (fast_ln(acc[mt][nt][2]) - CA_SHIFT);
            stg[(r0 + 8) * 68 + c0i + 1] = mx1[mt] + T_VAL * (fast_ln(acc[mt][nt][3]) - CA_SHIFT);
        }
    }
    __syncthreads();

    #pragma unroll
    for (int s = 0; s < 4; s++) {          // 2048 float4 chunks / 512 threads
        const int i = tid + s * 512;
        const int r = i >> 4, c4i = i & 15;
        float4 v = *(float4*)&stg[r * 68 + c4i * 4];
        *(float4*)&out[(size_t)(bm + r) * NDIM + bn + c4i * 4] = v;
    }
}

// ---------------- launch ----------------

extern "C" void kernel_launch(void* const* d_in, const int* in_sizes, int n_in,
                              void* d_out, int out_size)
{
    const float* x = (const float*)d_in[0];
    const float* W = (const float*)d_in[1];
    int nx = in_sizes[0], nw = in_sizes[1];
    if (nx == NDIM * KDIM && nw != NDIM * KDIM) {   // input-order safety
        const float* t = x; x = W; W = t;
        int ts = nx; nx = nw; nw = ts;
    }
    const int B = nx / KDIM;   // 2048

    cudaFuncSetAttribute(tropical_kernel,
                         cudaFuncAttributeMaxDynamicSharedMemorySize, SMEM_TOTAL);
    dim3 grid(NDIM / 64, B / 128);   // (8,16) = 128 CTAs
    tropical_kernel<<<grid, 512, SMEM_TOTAL>>>(x, W, (float*)d_out);
}